// round 1
// baseline (speedup 1.0000x reference)
#include <cuda_runtime.h>

// Problem constants
#define BATCH   64
#define TLEN    8192
#define DECL    64
#define NWIN    (TLEN - DECL)      // 8128
#define CHUNKS  8
#define WPC     (NWIN / CHUNKS)    // 1016 windows per chunk
#define TPB     128
#define WPT     8                  // windows per thread (128*8 = 1024 >= 1016)

// smem x tile: local indices 0..1087 needed (l0max=1016, ring reads to l0+71)
#define XTILE   1088
#define XTILEP  (XTILE + XTILE / 8)   // padded size (i -> i + i/8)

// Cross-block combine scratch (zero-init by default; kernel restores zeros
// after use so every graph replay sees the same initial state).
__device__ unsigned long long g_best[BATCH]; // holds max over ~key
__device__ unsigned int       g_cnt[BATCH];

__device__ __forceinline__ int padi(int i) { return i + (i >> 3); }

__global__ __launch_bounds__(TPB, 8)
void match_kernel(const float* __restrict__ X_in,
                  const float* __restrict__ X_out,
                  float* __restrict__ out)
{
    __shared__ float xs[XTILEP];
    __shared__ float ys[DECL];
    __shared__ unsigned long long red[TPB / 32];
    __shared__ int lastFlag;

    const int c   = blockIdx.x;     // chunk
    const int b   = blockIdx.y;     // batch
    const int tid = threadIdx.x;

    const float* xb = X_in + (size_t)b * TLEN;
    const int base  = c * WPC;      // first window of this chunk

    // Load x tile (guard tail of last chunk) and y
    for (int i = tid; i < XTILE; i += TPB) {
        int g = base + i;
        xs[padi(i)] = (g < TLEN) ? xb[g] : 0.0f;
    }
    if (tid < DECL) ys[tid] = X_out[b * DECL + tid];
    __syncthreads();

    const int l0 = tid * WPT;       // local index of this thread's first window

    // Sliding 8-register ring over x: ring holds x[l0+j .. l0+j+7],
    // element (l0+j+w) lives at slot (j+w)&7.
    float ring[8];
    #pragma unroll
    for (int w = 0; w < 8; ++w) ring[w] = xs[padi(l0 + w)];

    float acc0 = 0.f, acc1 = 0.f, acc2 = 0.f, acc3 = 0.f;
    float acc4 = 0.f, acc5 = 0.f, acc6 = 0.f, acc7 = 0.f;
    float sx2  = 0.f;               // sum x^2 over window w=0

    #pragma unroll
    for (int j = 0; j < DECL; ++j) {
        float yj = ys[j];
        acc0 = fmaf(ring[(j + 0) & 7], yj, acc0);
        acc1 = fmaf(ring[(j + 1) & 7], yj, acc1);
        acc2 = fmaf(ring[(j + 2) & 7], yj, acc2);
        acc3 = fmaf(ring[(j + 3) & 7], yj, acc3);
        acc4 = fmaf(ring[(j + 4) & 7], yj, acc4);
        acc5 = fmaf(ring[(j + 5) & 7], yj, acc5);
        acc6 = fmaf(ring[(j + 6) & 7], yj, acc6);
        acc7 = fmaf(ring[(j + 7) & 7], yj, acc7);
        float v = ring[j & 7];      // element leaving: x[l0+j]
        sx2 = fmaf(v, v, sx2);
        ring[j & 7] = xs[padi(l0 + j + 8)];
    }
    // After the loop ring[i] = x[l0 + 64 + i], i = 0..7.

    float acc[8]   = {acc0, acc1, acc2, acc3, acc4, acc5, acc6, acc7};
    float score[8];
    score[0] = sx2 - 2.0f * acc[0];
    float s = sx2;
    #pragma unroll
    for (int w = 1; w < 8; ++w) {
        float xin  = ring[w - 1];           // x[l0 + w + 63]
        float xout = xs[padi(l0 + w - 1)];  // x[l0 + w - 1]
        s = fmaf(xin, xin, s);
        s = fmaf(-xout, xout, s);
        score[w] = s - 2.0f * acc[w];
    }

    // Thread-local argmin with first-index tie-break, packed as monotonic key.
    unsigned long long bestik = 0ULL;       // max over ~key
    #pragma unroll
    for (int w = 0; w < 8; ++w) {
        int lw    = l0 + w;
        int gidx  = base + lw;
        bool valid = (lw < WPC);
        float sc  = valid ? score[w] : __int_as_float(0x7F800000); // +inf
        unsigned u = __float_as_uint(sc);
        unsigned m = u ^ ((unsigned)((int)u >> 31) | 0x80000000u); // monotonic map
        unsigned long long key = ((unsigned long long)m << 32) | (unsigned)gidx;
        unsigned long long ik  = ~key;      // max(ik) == min(key); tie -> smaller idx
        bestik = bestik > ik ? bestik : ik;
    }

    // Warp reduce (max over ~key)
    #pragma unroll
    for (int off = 16; off; off >>= 1) {
        unsigned long long o = __shfl_down_sync(0xFFFFFFFFu, bestik, off);
        bestik = bestik > o ? bestik : o;
    }
    if ((tid & 31) == 0) red[tid >> 5] = bestik;
    __syncthreads();

    if (tid == 0) {
        unsigned long long k = red[0];
        #pragma unroll
        for (int i = 1; i < TPB / 32; ++i) k = k > red[i] ? k : red[i];
        atomicMax(&g_best[b], k);
        __threadfence();
        unsigned prev = atomicAdd(&g_cnt[b], 1u);
        lastFlag = (prev == CHUNKS - 1) ? 1 : 0;
    }
    __syncthreads();

    // Last block for this batch gathers the output and restores scratch.
    if (lastFlag) {
        unsigned long long k = atomicMax(&g_best[b], 0ULL); // read current value
        int start = (int)((~k) & 0xFFFFFFFFull);
        if (tid < DECL) out[b * DECL + tid] = xb[start + tid];
        __syncthreads();
        if (tid == 0) { g_best[b] = 0ULL; g_cnt[b] = 0u; }
    }
}

extern "C" void kernel_launch(void* const* d_in, const int* in_sizes, int n_in,
                              void* d_out, int out_size)
{
    // inputs: 0=feats_in (unused), 1=X_in, 2=feats_out (unused), 3=X_out
    const float* X_in  = (const float*)d_in[1];
    const float* X_out = (const float*)d_in[3];
    float* out = (float*)d_out;

    dim3 grid(CHUNKS, BATCH);
    match_kernel<<<grid, TPB>>>(X_in, X_out, out);
}